// round 5
// baseline (speedup 1.0000x reference)
#include <cuda_runtime.h>
#include <cstdint>

#define PI_F 3.14159265358979323846f
#define LOG2E_F 1.44269504088896340736f

constexpr int C_IN   = 256;
constexpr int HW     = 256 * 256;      // 65536
constexpr int BATCH  = 8;
constexpr int PPT    = 2;              // pixels per thread
constexpr int NTHR   = 128;
constexpr int PPB    = NTHR * PPT;     // 256 pixels per block

constexpr int RING_CH  = 8;            // ring capacity in channels
constexpr int GROUP_CH = 2;            // channels per cp.async group
constexpr int NGROUPS  = C_IN / GROUP_CH;   // 128

// ---- fast math helpers (MUFU-based) ----
__device__ __forceinline__ float ex2_(float x) {
    float y; asm("ex2.approx.f32 %0, %1;" : "=f"(y) : "f"(x)); return y;
}
__device__ __forceinline__ float rcp_(float x) {
    float y; asm("rcp.approx.f32 %0, %1;" : "=f"(y) : "f"(x)); return y;
}
__device__ __forceinline__ float rsq_(float x) {
    float y; asm("rsqrt.approx.f32 %0, %1;" : "=f"(y) : "f"(x)); return y;
}
__device__ __forceinline__ float sigmoid_(float x) {
    return rcp_(1.0f + ex2_(-LOG2E_F * x));
}
__device__ __forceinline__ float tanh_(float x) {
    return 1.0f - 2.0f * rcp_(1.0f + ex2_(2.0f * LOG2E_F * x));
}

// ---- cp.async helpers ----
__device__ __forceinline__ void cpa16_(void* smem_dst, const void* gsrc) {
    unsigned s = (unsigned)__cvta_generic_to_shared(smem_dst);
    asm volatile("cp.async.cg.shared.global [%0], [%1], 16;\n"
                 :: "r"(s), "l"(gsrc) : "memory");
}
__device__ __forceinline__ void cpa_commit_() {
    asm volatile("cp.async.commit_group;\n" ::: "memory");
}
__device__ __forceinline__ void cpa_wait2_() {
    asm volatile("cp.async.wait_group 2;\n" ::: "memory");
}

__global__ __launch_bounds__(NTHR, 10)
void brdf_fused_kernel(const float* __restrict__ feats,
                       const float* __restrict__ wi,
                       const float* __restrict__ wo,
                       const float* __restrict__ w_normal,
                       const float* __restrict__ w_albedo,
                       const float* __restrict__ w_rough,
                       const float* __restrict__ w_fresnel,
                       float* __restrict__ out_imgs,
                       float* __restrict__ out_data)
{
    // Weights in 3 aligned split arrays: 3 LDS broadcasts per channel.
    __shared__ float4 swA[C_IN];   // n0 n1 n2 a0
    __shared__ float4 swB[C_IN];   // a1 a2 r  f0
    __shared__ float2 swC[C_IN];   // f1 f2
    // feats ring: 8 channels x 256 pixel-floats = 8 KB. Channel slot ch&7
    // holds the block's 256 pixels of that channel in pixel order.
    __shared__ float ring[RING_CH * PPB];

    const int tid = threadIdx.x;
    for (int i = tid; i < C_IN; i += NTHR) {
        swA[i] = make_float4(w_normal[0 * C_IN + i], w_normal[1 * C_IN + i],
                             w_normal[2 * C_IN + i], w_albedo[0 * C_IN + i]);
        swB[i] = make_float4(w_albedo[1 * C_IN + i], w_albedo[2 * C_IN + i],
                             w_rough[i],             w_fresnel[0 * C_IN + i]);
        swC[i] = make_float2(w_fresnel[1 * C_IN + i], w_fresnel[2 * C_IN + i]);
    }
    __syncthreads();

    const long long blockpix = (long long)blockIdx.x * PPB;
    const int b   = (int)(blockpix / HW);
    const int hwb = (int)(blockpix % HW);
    const long long gpix = blockpix + tid * PPT;

    const int half = tid >> 1;   // 0..63: float4 slot this thread loads
    const int par  = tid & 1;    // channel parity this thread loads

    // Loader pointer: channel (0 + par), this thread's 16B slice.
    const float* gl = feats + (size_t)b * C_IN * HW + hwb
                    + (size_t)par * HW + half * 4;

    float acc[10][2];
#pragma unroll
    for (int o = 0; o < 10; ++o) { acc[o][0] = 0.f; acc[o][1] = 0.f; }

    // ---- prologue: groups 0..2 (channels 0..5), 3 groups in flight ----
#pragma unroll
    for (int gidx = 0; gidx < 3; ++gidx) {
        const int ch = gidx * GROUP_CH + par;
        cpa16_(&ring[(ch & (RING_CH - 1)) * PPB + half * 4],
               gl + (size_t)gidx * GROUP_CH * HW);
        cpa_commit_();
    }

    const float* glp = gl + (size_t)3 * GROUP_CH * HW;  // next channel to fetch (+par)

    // ---- main loop: 128 groups of 2 channels ----
#pragma unroll 2
    for (int g2 = 0; g2 < NGROUPS; ++g2) {
        cpa_wait2_();      // this thread's group g2 landed
        __syncwarp();      // producer lanes (t / t^1) are same warp

        const int c = g2 * GROUP_CH;
#pragma unroll
        for (int d = 0; d < GROUP_CH; ++d) {
            const int ch = c + d;
            const float2 f = *reinterpret_cast<const float2*>(
                &ring[(ch & (RING_CH - 1)) * PPB + tid * 2]);
            const float4 wA = swA[ch];
            const float4 wB = swB[ch];
            const float2 wC = swC[ch];
            const float w[10] = {wA.x, wA.y, wA.z, wA.w, wB.x,
                                 wB.y, wB.z, wB.w, wC.x, wC.y};
#pragma unroll
            for (int o = 0; o < 10; ++o) {
                acc[o][0] = fmaf(f.x, w[o], acc[o][0]);
                acc[o][1] = fmaf(f.y, w[o], acc[o][1]);
            }
        }

        // issue group g2+3 (channels c+6, c+7); uniform empty commit in tail.
        const int cn = c + 3 * GROUP_CH;
        if (cn < C_IN) {
            cpa16_(&ring[((cn + par) & (RING_CH - 1)) * PPB + half * 4], glp);
        }
        glp += (size_t)GROUP_CH * HW;
        cpa_commit_();
    }

    const float inv_pi = 1.0f / PI_F;

    // wi/wo: 2 px * 3 comps = 6 contiguous floats, 8B-aligned.
    float wiL[6], woL[6];
    {
        const float2* wip2 = reinterpret_cast<const float2*>(wi + gpix * 3);
        const float2* wop2 = reinterpret_cast<const float2*>(wo + gpix * 3);
#pragma unroll
        for (int q = 0; q < 3; ++q) {
            float2 a  = __ldg(&wip2[q]);
            float2 bq = __ldg(&wop2[q]);
            wiL[q * 2 + 0] = a.x;  wiL[q * 2 + 1] = a.y;
            woL[q * 2 + 0] = bq.x; woL[q * 2 + 1] = bq.y;
        }
    }

    float img[6];

#pragma unroll
    for (int j = 0; j < PPT; ++j) {
        const long long g = gpix + j;

        // ---- activations ----
        float nx = tanh_(acc[0][j]);
        float ny = tanh_(acc[1][j]);
        float nz = tanh_(acc[2][j]);
        {
            const float inv = rsq_(fmaxf(nx * nx + ny * ny + nz * nz, 1e-24f));
            nx *= inv; ny *= inv; nz *= inv;
        }
        const float al0 = sigmoid_(acc[3][j]);
        const float al1 = sigmoid_(acc[4][j]);
        const float al2 = sigmoid_(acc[5][j]);
        float rough = sigmoid_(acc[6][j]);
        rough = fminf(fmaxf(rough, 0.001f), 1.0f);
        const float f0x = sigmoid_(acc[7][j]);
        const float f0y = sigmoid_(acc[8][j]);
        const float f0z = sigmoid_(acc[9][j]);

        // ---- light/view vectors ----
        float lx = wiL[j * 3 + 0], ly = wiL[j * 3 + 1], lz = wiL[j * 3 + 2];
        float vx = woL[j * 3 + 0], vy = woL[j * 3 + 1], vz = woL[j * 3 + 2];
        {
            const float il = rsq_(fmaxf(lx * lx + ly * ly + lz * lz, 1e-24f));
            lx *= il; ly *= il; lz *= il;
        }
        {
            const float iv = rsq_(fmaxf(vx * vx + vy * vy + vz * vz, 1e-24f));
            vx *= iv; vy *= iv; vz *= iv;
        }
        float hx = lx + vx, hy = ly + vy, hz = lz + vz;
        {
            const float ih = rsq_(fmaxf(hx * hx + hy * hy + hz * hz, 1e-24f));
            hx *= ih; hy *= ih; hz *= ih;
        }

        const float NdotH = fmaxf(nx * hx + ny * hy + nz * hz, 1e-8f);
        const float NdotL = fmaxf(nx * lx + ny * ly + nz * lz, 1e-8f);
        const float NdotV = fmaxf(nx * vx + ny * vy + nz * vz, 1e-8f);
        const float VdotH = fmaxf(vx * hx + vy * hy + vz * hz, 1e-8f);

        // ---- GGX ----
        const float alpha = rough * rough;
        const float a2    = alpha * alpha;
        const float den   = fmaf(NdotH * NdotH, a2 - 1.0f, 1.0f);
        const float D     = a2 * rcp_(PI_F * den * den);
        const float Fe    = ex2_(fmaf(-5.55473f, VdotH, -6.98316f) * VdotH);
        const float k     = alpha * 0.5f;
        const float G     = rcp_(fmaf(NdotL, 1.0f - k, k)) *
                            rcp_(fmaf(NdotV, 1.0f - k, k));
        const float DG    = 0.25f * D * G;

        const float F0 = fmaf(1.0f - f0x, Fe, f0x);
        const float F1 = fmaf(1.0f - f0y, Fe, f0y);
        const float F2 = fmaf(1.0f - f0z, Fe, f0z);

        img[j * 3 + 0] = fmaxf((al0 * (1.0f - f0x) * inv_pi + DG * F0) * NdotL, 0.0f);
        img[j * 3 + 1] = fmaxf((al1 * (1.0f - f0y) * inv_pi + DG * F1) * NdotL, 0.0f);
        img[j * 3 + 2] = fmaxf((al2 * (1.0f - f0z) * inv_pi + DG * F2) * NdotL, 0.0f);

        // ---- write data [B,H,W,12]: normal, albedo, rough x3, fresnel ----
        float4* dp = reinterpret_cast<float4*>(out_data + g * 12);
        dp[0] = make_float4(nx, ny, nz, al0);
        dp[1] = make_float4(al1, al2, rough, rough);
        dp[2] = make_float4(rough, f0x, f0y, f0z);
    }

    // ---- write imgs [B,H,W,3]: 6 contiguous floats, 8B-aligned ----
    {
        float2* ip = reinterpret_cast<float2*>(out_imgs + gpix * 3);
        ip[0] = make_float2(img[0], img[1]);
        ip[1] = make_float2(img[2], img[3]);
        ip[2] = make_float2(img[4], img[5]);
    }
}

extern "C" void kernel_launch(void* const* d_in, const int* in_sizes, int n_in,
                              void* d_out, int out_size)
{
    const float* feats     = (const float*)d_in[0];
    const float* wi        = (const float*)d_in[1];
    const float* wo        = (const float*)d_in[2];
    const float* w_normal  = (const float*)d_in[3];
    const float* w_albedo  = (const float*)d_in[4];
    const float* w_rough   = (const float*)d_in[5];
    const float* w_fresnel = (const float*)d_in[6];

    float* out = (float*)d_out;
    const long long NPIX = (long long)BATCH * HW;   // 524288
    float* out_imgs = out;                           // [B,H,W,3]
    float* out_data = out + NPIX * 3;                // [B,H,W,12]

    const int blocks = (int)(NPIX / PPB);            // 2048
    brdf_fused_kernel<<<blocks, NTHR>>>(feats, wi, wo,
                                        w_normal, w_albedo, w_rough, w_fresnel,
                                        out_imgs, out_data);
}

// round 6
// speedup vs baseline: 1.0769x; 1.0769x over previous
#include <cuda_runtime.h>
#include <cstdint>

#define PI_F 3.14159265358979323846f
#define LOG2E_F 1.44269504088896340736f

constexpr int C_IN    = 256;
constexpr int HW      = 256 * 256;     // 65536
constexpr int BATCH   = 8;
constexpr int NTHR    = 128;
constexpr int HALF_T  = 64;            // threads per channel-half
constexpr int PPT     = 4;             // pixels per thread in the conv loop
constexpr int PPB     = HALF_T * PPT;  // 256 pixels per block
constexpr int CH_HALF = C_IN / 2;      // 128 channels per half
constexpr int RING_CH = 8;             // ring slots (channels) per half
constexpr int GROUP_CH = 2;            // channels per commit group
constexpr int NGROUPS  = CH_HALF / GROUP_CH;  // 64

// ---- fast math helpers (MUFU-based) ----
__device__ __forceinline__ float ex2_(float x) {
    float y; asm("ex2.approx.f32 %0, %1;" : "=f"(y) : "f"(x)); return y;
}
__device__ __forceinline__ float rcp_(float x) {
    float y; asm("rcp.approx.f32 %0, %1;" : "=f"(y) : "f"(x)); return y;
}
__device__ __forceinline__ float rsq_(float x) {
    float y; asm("rsqrt.approx.f32 %0, %1;" : "=f"(y) : "f"(x)); return y;
}
__device__ __forceinline__ float sigmoid_(float x) {
    return rcp_(1.0f + ex2_(-LOG2E_F * x));
}
__device__ __forceinline__ float tanh_(float x) {
    return 1.0f - 2.0f * rcp_(1.0f + ex2_(2.0f * LOG2E_F * x));
}

// ---- cp.async helpers ----
__device__ __forceinline__ void cpa16_(void* smem_dst, const void* gsrc) {
    unsigned s = (unsigned)__cvta_generic_to_shared(smem_dst);
    asm volatile("cp.async.cg.shared.global [%0], [%1], 16;\n"
                 :: "r"(s), "l"(gsrc) : "memory");
}
__device__ __forceinline__ void cpa_commit_() {
    asm volatile("cp.async.commit_group;\n" ::: "memory");
}
__device__ __forceinline__ void cpa_wait2_() {
    asm volatile("cp.async.wait_group 2;\n" ::: "memory");
}
__device__ __forceinline__ void cpa_wait0_() {
    asm volatile("cp.async.wait_group 0;\n" ::: "memory");
}

__global__ __launch_bounds__(NTHR, 8)
void brdf_fused_kernel(const float* __restrict__ feats,
                       const float* __restrict__ wi,
                       const float* __restrict__ wo,
                       const float* __restrict__ w_normal,
                       const float* __restrict__ w_albedo,
                       const float* __restrict__ w_rough,
                       const float* __restrict__ w_fresnel,
                       float* __restrict__ out_imgs,
                       float* __restrict__ out_data)
{
    // Weights in 3 aligned split arrays: 3 LDS broadcasts per channel.
    __shared__ float4 swA[C_IN];   // n0 n1 n2 a0
    __shared__ float4 swB[C_IN];   // a1 a2 r  f0
    __shared__ float2 swC[C_IN];   // f1 f2
    // 16 KB buffer: during the loop it is two 8-channel rings (one per half,
    // 8 ch x 64 threads x 16 B each); after the loop it is reused as the
    // 10x256-float accumulator merge buffer.
    __shared__ __align__(16) float smembuf[2 * RING_CH * HALF_T * 4];

    const int tid = threadIdx.x;
    for (int i = tid; i < C_IN; i += NTHR) {
        swA[i] = make_float4(w_normal[0 * C_IN + i], w_normal[1 * C_IN + i],
                             w_normal[2 * C_IN + i], w_albedo[0 * C_IN + i]);
        swB[i] = make_float4(w_albedo[1 * C_IN + i], w_albedo[2 * C_IN + i],
                             w_rough[i],             w_fresnel[0 * C_IN + i]);
        swC[i] = make_float2(w_fresnel[1 * C_IN + i], w_fresnel[2 * C_IN + i]);
    }
    __syncthreads();

    const int h  = tid >> 6;        // channel-half: 0 or 1
    const int lt = tid & 63;        // lane within half

    const long long blockpix = (long long)blockIdx.x * PPB;
    const int b   = (int)(blockpix / HW);
    const int hwb = (int)(blockpix % HW);

    // This thread's 16B pixel slice in channel (h*128 + 0).
    const float* gp = feats + (size_t)b * C_IN * HW
                    + (size_t)(h * CH_HALF) * HW + hwb + lt * 4;

    float4* ring = reinterpret_cast<float4*>(smembuf) + h * RING_CH * HALF_T;

    float acc[10][4];
#pragma unroll
    for (int o = 0; o < 10; ++o)
#pragma unroll
        for (int j = 0; j < 4; ++j) acc[o][j] = 0.f;

    // ---- prologue: groups 0..2 (local channels 0..5), 3 groups in flight ----
#pragma unroll
    for (int gi = 0; gi < 3; ++gi) {
        const int c0 = gi * GROUP_CH;
        cpa16_(&ring[((c0)     & (RING_CH - 1)) * HALF_T + lt], gp + (size_t)(c0)     * HW);
        cpa16_(&ring[((c0 + 1) & (RING_CH - 1)) * HALF_T + lt], gp + (size_t)(c0 + 1) * HW);
        cpa_commit_();
    }
    const float* glp = gp + (size_t)3 * GROUP_CH * HW;

    // ---- main loop: 64 groups of 2 channels (this half's 128 channels) ----
#pragma unroll 4
    for (int g2 = 0; g2 < NGROUPS; ++g2) {
        cpa_wait2_();      // own group g2 landed (self-produced, no sync needed)
        const int c = g2 * GROUP_CH;

#pragma unroll
        for (int d = 0; d < GROUP_CH; ++d) {
            const int ch = c + d;
            const float4 f = ring[(ch & (RING_CH - 1)) * HALF_T + lt];
            const int cw = h * CH_HALF + ch;
            const float4 wA = swA[cw];
            const float4 wB = swB[cw];
            const float2 wC = swC[cw];
            const float w[10] = {wA.x, wA.y, wA.z, wA.w, wB.x,
                                 wB.y, wB.z, wB.w, wC.x, wC.y};
            const float fv[4] = {f.x, f.y, f.z, f.w};
#pragma unroll
            for (int o = 0; o < 10; ++o)
#pragma unroll
                for (int j = 0; j < 4; ++j)
                    acc[o][j] = fmaf(fv[j], w[o], acc[o][j]);
        }

        const int cn = c + 3 * GROUP_CH;
        if (cn < CH_HALF) {
            cpa16_(&ring[((cn)     & (RING_CH - 1)) * HALF_T + lt], glp);
            cpa16_(&ring[((cn + 1) & (RING_CH - 1)) * HALF_T + lt], glp + HW);
        }
        glp += (size_t)GROUP_CH * HW;
        cpa_commit_();
    }

    // ---- merge the two channel-halves through smem (ring is dead now) ----
    cpa_wait0_();          // retire all async copies before aliasing the ring
    __syncthreads();

    float* merge = smembuf;          // [o][px] : 10 x 256 floats
    if (h == 1) {
#pragma unroll
        for (int o = 0; o < 10; ++o)
            *reinterpret_cast<float4*>(&merge[o * PPB + lt * 4]) =
                make_float4(acc[o][0], acc[o][1], acc[o][2], acc[o][3]);
    }
    __syncthreads();
    if (h == 0) {
#pragma unroll
        for (int o = 0; o < 10; ++o) {
            float4* mp = reinterpret_cast<float4*>(&merge[o * PPB + lt * 4]);
            float4 m = *mp;
            m.x += acc[o][0]; m.y += acc[o][1];
            m.z += acc[o][2]; m.w += acc[o][3];
            *mp = m;
        }
    }
    __syncthreads();

    // ---- epilogue: all 128 threads, 2 pixels each ----
    const long long gpix = blockpix + tid * 2;

    float a2[10][2];
#pragma unroll
    for (int o = 0; o < 10; ++o) {
        const float2 m = *reinterpret_cast<const float2*>(&merge[o * PPB + tid * 2]);
        a2[o][0] = m.x; a2[o][1] = m.y;
    }

    const float inv_pi = 1.0f / PI_F;

    // wi/wo: 2 px * 3 comps = 6 contiguous floats, 8B-aligned.
    float wiL[6], woL[6];
    {
        const float2* wip2 = reinterpret_cast<const float2*>(wi + gpix * 3);
        const float2* wop2 = reinterpret_cast<const float2*>(wo + gpix * 3);
#pragma unroll
        for (int q = 0; q < 3; ++q) {
            float2 a  = __ldg(&wip2[q]);
            float2 bq = __ldg(&wop2[q]);
            wiL[q * 2 + 0] = a.x;  wiL[q * 2 + 1] = a.y;
            woL[q * 2 + 0] = bq.x; woL[q * 2 + 1] = bq.y;
        }
    }

    float img[6];

#pragma unroll
    for (int j = 0; j < 2; ++j) {
        const long long g = gpix + j;

        // ---- activations ----
        float nx = tanh_(a2[0][j]);
        float ny = tanh_(a2[1][j]);
        float nz = tanh_(a2[2][j]);
        {
            const float inv = rsq_(fmaxf(nx * nx + ny * ny + nz * nz, 1e-24f));
            nx *= inv; ny *= inv; nz *= inv;
        }
        const float al0 = sigmoid_(a2[3][j]);
        const float al1 = sigmoid_(a2[4][j]);
        const float al2 = sigmoid_(a2[5][j]);
        float rough = sigmoid_(a2[6][j]);
        rough = fminf(fmaxf(rough, 0.001f), 1.0f);
        const float f0x = sigmoid_(a2[7][j]);
        const float f0y = sigmoid_(a2[8][j]);
        const float f0z = sigmoid_(a2[9][j]);

        // ---- light/view vectors ----
        float lx = wiL[j * 3 + 0], ly = wiL[j * 3 + 1], lz = wiL[j * 3 + 2];
        float vx = woL[j * 3 + 0], vy = woL[j * 3 + 1], vz = woL[j * 3 + 2];
        {
            const float il = rsq_(fmaxf(lx * lx + ly * ly + lz * lz, 1e-24f));
            lx *= il; ly *= il; lz *= il;
        }
        {
            const float iv = rsq_(fmaxf(vx * vx + vy * vy + vz * vz, 1e-24f));
            vx *= iv; vy *= iv; vz *= iv;
        }
        float hx = lx + vx, hy = ly + vy, hz = lz + vz;
        {
            const float ih = rsq_(fmaxf(hx * hx + hy * hy + hz * hz, 1e-24f));
            hx *= ih; hy *= ih; hz *= ih;
        }

        const float NdotH = fmaxf(nx * hx + ny * hy + nz * hz, 1e-8f);
        const float NdotL = fmaxf(nx * lx + ny * ly + nz * lz, 1e-8f);
        const float NdotV = fmaxf(nx * vx + ny * vy + nz * vz, 1e-8f);
        const float VdotH = fmaxf(vx * hx + vy * hy + vz * hz, 1e-8f);

        // ---- GGX ----
        const float alpha = rough * rough;
        const float a2g   = alpha * alpha;
        const float den   = fmaf(NdotH * NdotH, a2g - 1.0f, 1.0f);
        const float D     = a2g * rcp_(PI_F * den * den);
        const float Fe    = ex2_(fmaf(-5.55473f, VdotH, -6.98316f) * VdotH);
        const float k     = alpha * 0.5f;
        const float G     = rcp_(fmaf(NdotL, 1.0f - k, k)) *
                            rcp_(fmaf(NdotV, 1.0f - k, k));
        const float DG    = 0.25f * D * G;

        const float F0 = fmaf(1.0f - f0x, Fe, f0x);
        const float F1 = fmaf(1.0f - f0y, Fe, f0y);
        const float F2 = fmaf(1.0f - f0z, Fe, f0z);

        img[j * 3 + 0] = fmaxf((al0 * (1.0f - f0x) * inv_pi + DG * F0) * NdotL, 0.0f);
        img[j * 3 + 1] = fmaxf((al1 * (1.0f - f0y) * inv_pi + DG * F1) * NdotL, 0.0f);
        img[j * 3 + 2] = fmaxf((al2 * (1.0f - f0z) * inv_pi + DG * F2) * NdotL, 0.0f);

        // ---- write data [B,H,W,12]: normal, albedo, rough x3, fresnel ----
        float4* dp = reinterpret_cast<float4*>(out_data + g * 12);
        dp[0] = make_float4(nx, ny, nz, al0);
        dp[1] = make_float4(al1, al2, rough, rough);
        dp[2] = make_float4(rough, f0x, f0y, f0z);
    }

    // ---- write imgs [B,H,W,3]: 6 contiguous floats, 8B-aligned ----
    {
        float2* ip = reinterpret_cast<float2*>(out_imgs + gpix * 3);
        ip[0] = make_float2(img[0], img[1]);
        ip[1] = make_float2(img[2], img[3]);
        ip[2] = make_float2(img[4], img[5]);
    }
}

extern "C" void kernel_launch(void* const* d_in, const int* in_sizes, int n_in,
                              void* d_out, int out_size)
{
    const float* feats     = (const float*)d_in[0];
    const float* wi        = (const float*)d_in[1];
    const float* wo        = (const float*)d_in[2];
    const float* w_normal  = (const float*)d_in[3];
    const float* w_albedo  = (const float*)d_in[4];
    const float* w_rough   = (const float*)d_in[5];
    const float* w_fresnel = (const float*)d_in[6];

    float* out = (float*)d_out;
    const long long NPIX = (long long)BATCH * HW;   // 524288
    float* out_imgs = out;                           // [B,H,W,3]
    float* out_data = out + NPIX * 3;                // [B,H,W,12]

    const int blocks = (int)(NPIX / PPB);            // 2048
    brdf_fused_kernel<<<blocks, NTHR>>>(feats, wi, wo,
                                        w_normal, w_albedo, w_rough, w_fresnel,
                                        out_imgs, out_data);
}